// round 2
// baseline (speedup 1.0000x reference)
#include <cuda_runtime.h>
#include <cstdint>

// Problem dims (fixed by the dataset)
#define M_DIM 8192
#define K_DIM 4096
#define N_DIM 4096

// ---------------------------------------------------------------------------
// Scratch: static __device__ globals (no runtime allocation allowed).
//   g_w8 : int8 weights [N, K]
//   g_xa / g_xb : int8 activation ping-pong buffers [M, K]
// Kernels reference these directly (no cudaGetSymbolAddress on host).
// ---------------------------------------------------------------------------
__device__ __align__(128) int8_t g_w8[(size_t)N_DIM * K_DIM];
__device__ __align__(128) int8_t g_xa[(size_t)M_DIM * K_DIM];
__device__ __align__(128) int8_t g_xb[(size_t)M_DIM * K_DIM];

// ---------------------------------------------------------------------------
// Weight conversion: int32 -> int8 (values already in [-128,127])
// ---------------------------------------------------------------------------
__global__ void prep_w_kernel(const int* __restrict__ w) {
    size_t i = (size_t)blockIdx.x * blockDim.x + threadIdx.x;
    size_t n4 = (size_t)N_DIM * K_DIM / 4;
    if (i < n4) {
        int4 v = reinterpret_cast<const int4*>(w)[i];
        char4 c;
        c.x = (char)v.x; c.y = (char)v.y; c.z = (char)v.z; c.w = (char)v.w;
        reinterpret_cast<char4*>(g_w8)[i] = c;
    }
}

// ---------------------------------------------------------------------------
// Input quantization: fp32 -> int8
//   q = clip(round(x/s) + zp, 0, 255) - zp  ==  clip(round(x/s), -zp, 255-zp)
// ---------------------------------------------------------------------------
__global__ void quant_x_kernel(const float* __restrict__ x,
                               const float* __restrict__ s_in_p,
                               const int* __restrict__ zp_p) {
    size_t i = (size_t)blockIdx.x * blockDim.x + threadIdx.x;
    size_t n4 = (size_t)M_DIM * K_DIM / 4;
    if (i >= n4) return;
    float s  = s_in_p[0];
    float zp = (float)zp_p[0];
    float lo = 0.0f - zp, hi = 255.0f - zp;
    float4 v = reinterpret_cast<const float4*>(x)[i];
    float q0 = fminf(fmaxf(rintf(__fdiv_rn(v.x, s)), lo), hi);
    float q1 = fminf(fmaxf(rintf(__fdiv_rn(v.y, s)), lo), hi);
    float q2 = fminf(fmaxf(rintf(__fdiv_rn(v.z, s)), lo), hi);
    float q3 = fminf(fmaxf(rintf(__fdiv_rn(v.w, s)), lo), hi);
    char4 c;
    c.x = (char)(int)q0; c.y = (char)(int)q1; c.z = (char)(int)q2; c.w = (char)(int)q3;
    reinterpret_cast<char4*>(g_xa)[i] = c;
}

// ---------------------------------------------------------------------------
// PTX helpers
// ---------------------------------------------------------------------------
__device__ __forceinline__ void cp16(uint32_t smem_dst, const void* gmem_src) {
    asm volatile("cp.async.cg.shared.global [%0], [%1], 16;\n"
                 :: "r"(smem_dst), "l"(gmem_src));
}

__device__ __forceinline__ void ldsm_x4(uint32_t& r0, uint32_t& r1, uint32_t& r2,
                                        uint32_t& r3, uint32_t addr) {
    asm volatile("ldmatrix.sync.aligned.m8n8.x4.shared.b16 {%0,%1,%2,%3}, [%4];"
                 : "=r"(r0), "=r"(r1), "=r"(r2), "=r"(r3) : "r"(addr));
}

__device__ __forceinline__ void imma16832(int* c, uint32_t a0, uint32_t a1,
                                          uint32_t a2, uint32_t a3,
                                          uint32_t b0, uint32_t b1) {
    asm volatile(
        "mma.sync.aligned.m16n8k32.row.col.s32.s8.s8.s32 "
        "{%0,%1,%2,%3}, {%4,%5,%6,%7}, {%8,%9}, {%0,%1,%2,%3};"
        : "+r"(c[0]), "+r"(c[1]), "+r"(c[2]), "+r"(c[3])
        : "r"(a0), "r"(a1), "r"(a2), "r"(a3), "r"(b0), "r"(b1));
}

// ---------------------------------------------------------------------------
// Int8 GEMM + fused dequant(+requant) epilogue.
//   C[m,n] = A[m,:] (int8) dot B[n,:] (int8)   -> int32  (exact)
//   y      = s_in * s_w[n] * C + bias[n]
//   LAYER 0: A = g_xa, requant int8 -> g_xb
//   LAYER 1: A = g_xb, requant int8 -> g_xa
//   LAYER 2: A = g_xa, float       -> out (harness d_out)
//
// Block tile 128x128, K-tile 64, 8 warps (2x4), warp tile 64x32.
// SMEM rows padded to 80 B (64 data + 16 pad) -> conflict-free 8-row ldmatrix.
// ---------------------------------------------------------------------------
#define KTILE 64
#define ROWB  80           // padded smem row stride in bytes
#define BUFB  (128 * ROWB) // 10240 bytes per tile buffer

template <int LAYER>
__global__ __launch_bounds__(256)
void qgemm_kernel(const float* __restrict__ bias,
                  const float* __restrict__ s_in_p,
                  const int* __restrict__ zp_p,
                  const float* __restrict__ s_w,
                  float* __restrict__ fout) {
    __shared__ __align__(128) int8_t sA[2][BUFB];
    __shared__ __align__(128) int8_t sB[2][BUFB];

    const int8_t* __restrict__ A = (LAYER == 1) ? g_xb : g_xa;
    int8_t* __restrict__ q_out   = (LAYER == 0) ? g_xb : g_xa;
    const int8_t* __restrict__ B = g_w8;

    const int tid  = threadIdx.x;
    const int lane = tid & 31;
    const int wid  = tid >> 5;
    const int m0 = blockIdx.y * 128;
    const int n0 = blockIdx.x * 128;
    const int wm = (wid >> 2) * 64;   // warp m offset within block
    const int wn = (wid & 3) * 32;    // warp n offset within block

    uint32_t sAu = (uint32_t)__cvta_generic_to_shared(&sA[0][0]);
    uint32_t sBu = (uint32_t)__cvta_generic_to_shared(&sB[0][0]);

    // ---- async tile loader: 128 rows x 64 B each of A and B ----
    auto load_tiles = [&](int buf, int kt) {
        int kbase = kt * KTILE;
#pragma unroll
        for (int i = 0; i < 2; i++) {
            int idx = (i << 8) + tid;         // 0..511
            int row = idx >> 2;
            int chb = (idx & 3) << 4;         // 0,16,32,48
            cp16(sAu + buf * BUFB + row * ROWB + chb,
                 A + (size_t)(m0 + row) * K_DIM + kbase + chb);
            cp16(sBu + buf * BUFB + row * ROWB + chb,
                 B + (size_t)(n0 + row) * K_DIM + kbase + chb);
        }
    };

    int acc[4][4][4];
#pragma unroll
    for (int mi = 0; mi < 4; mi++)
#pragma unroll
        for (int nj = 0; nj < 4; nj++)
#pragma unroll
            for (int r = 0; r < 4; r++) acc[mi][nj][r] = 0;

    const int NT = K_DIM / KTILE;   // 64

    load_tiles(0, 0);
    asm volatile("cp.async.commit_group;");

    // ldmatrix address components (per-thread, loop-invariant)
    const int q  = lane >> 3;       // matrix index 0..3
    const int rr = lane & 7;        // row within 8-row matrix

    for (int kt = 0; kt < NT; kt++) {
        int cur = kt & 1;
        if (kt + 1 < NT) {
            load_tiles(cur ^ 1, kt + 1);
            asm volatile("cp.async.commit_group;");
            asm volatile("cp.async.wait_group 1;");
        } else {
            asm volatile("cp.async.wait_group 0;");
        }
        __syncthreads();

        uint32_t sAb = sAu + cur * BUFB;
        uint32_t sBb = sBu + cur * BUFB;

#pragma unroll
        for (int ks = 0; ks < 2; ks++) {   // two k32 steps per 64-K tile
            // A fragments: ldsm matrices = (rows0-7,k0),(rows8-15,k0),(rows0-7,k1),(rows8-15,k1)
            uint32_t a[4][4];
            {
                int rhalf = q & 1, kc = q >> 1;
#pragma unroll
                for (int mi = 0; mi < 4; mi++) {
                    int row = wm + mi * 16 + rhalf * 8 + rr;
                    uint32_t addr = sAb + row * ROWB + ks * 32 + kc * 16;
                    ldsm_x4(a[mi][0], a[mi][1], a[mi][2], a[mi][3], addr);
                }
            }
            // B fragments: x4 covers two n8 tiles: matrices (j0,k0),(j0,k1),(j1,k0),(j1,k1)
            uint32_t b[4][2];
            {
                int ntile_sub = q >> 1, kcB = q & 1;
#pragma unroll
                for (int jp = 0; jp < 2; jp++) {
                    int nrow = wn + (jp * 2 + ntile_sub) * 8 + rr;
                    uint32_t addr = sBb + nrow * ROWB + ks * 32 + kcB * 16;
                    ldsm_x4(b[jp * 2][0], b[jp * 2][1],
                            b[jp * 2 + 1][0], b[jp * 2 + 1][1], addr);
                }
            }
#pragma unroll
            for (int mi = 0; mi < 4; mi++)
#pragma unroll
                for (int nj = 0; nj < 4; nj++)
                    imma16832(acc[mi][nj], a[mi][0], a[mi][1], a[mi][2], a[mi][3],
                              b[nj][0], b[nj][1]);
        }
        __syncthreads();
    }

    // ---- epilogue ----
    float s  = s_in_p[0];
    float zp = (float)zp_p[0];
    float lo = 0.0f - zp, hi = 255.0f - zp;

#pragma unroll
    for (int nj = 0; nj < 4; nj++) {
        int col = n0 + wn + nj * 8 + (lane & 3) * 2;
        float sw0 = s * __ldg(&s_w[col]);
        float sw1 = s * __ldg(&s_w[col + 1]);
        float bi0 = __ldg(&bias[col]);
        float bi1 = __ldg(&bias[col + 1]);
#pragma unroll
        for (int mi = 0; mi < 4; mi++) {
            int row = m0 + wm + mi * 16 + (lane >> 2);
            float y00 = fmaf((float)acc[mi][nj][0], sw0, bi0);
            float y01 = fmaf((float)acc[mi][nj][1], sw1, bi1);
            float y10 = fmaf((float)acc[mi][nj][2], sw0, bi0);
            float y11 = fmaf((float)acc[mi][nj][3], sw1, bi1);
            if (LAYER < 2) {
                float q00 = fminf(fmaxf(rintf(__fdiv_rn(y00, s)), lo), hi);
                float q01 = fminf(fmaxf(rintf(__fdiv_rn(y01, s)), lo), hi);
                float q10 = fminf(fmaxf(rintf(__fdiv_rn(y10, s)), lo), hi);
                float q11 = fminf(fmaxf(rintf(__fdiv_rn(y11, s)), lo), hi);
                char2 c0; c0.x = (char)(int)q00; c0.y = (char)(int)q01;
                char2 c1; c1.x = (char)(int)q10; c1.y = (char)(int)q11;
                *reinterpret_cast<char2*>(q_out + (size_t)row * N_DIM + col) = c0;
                *reinterpret_cast<char2*>(q_out + (size_t)(row + 8) * N_DIM + col) = c1;
            } else {
                float2 f0; f0.x = y00; f0.y = y01;
                float2 f1; f1.x = y10; f1.y = y11;
                *reinterpret_cast<float2*>(fout + (size_t)row * N_DIM + col) = f0;
                *reinterpret_cast<float2*>(fout + (size_t)(row + 8) * N_DIM + col) = f1;
            }
        }
    }
}

// ---------------------------------------------------------------------------
// kernel_launch: graph-capturable, allocation-free, launches only.
// Input order (metadata): input, weights, biases, input_scales,
//                         input_zero_points, weight_scales,
//                         weight_zero_points, output_dtype
// ---------------------------------------------------------------------------
extern "C" void kernel_launch(void* const* d_in, const int* in_sizes, int n_in,
                              void* d_out, int out_size) {
    const float* x    = (const float*)d_in[0];
    const int*   w    = (const int*)d_in[1];
    const float* bias = (const float*)d_in[2];
    const float* s_in = (const float*)d_in[3];
    const int*   zp   = (const int*)d_in[4];
    const float* s_w  = (const float*)d_in[5];

    // 1) weights int32 -> int8
    {
        size_t n4 = (size_t)N_DIM * K_DIM / 4;
        prep_w_kernel<<<(unsigned)((n4 + 255) / 256), 256>>>(w);
    }
    // 2) quantize input activations -> g_xa
    {
        size_t n4 = (size_t)M_DIM * K_DIM / 4;
        quant_x_kernel<<<(unsigned)((n4 + 255) / 256), 256>>>(x, s_in, zp);
    }
    // 3) three fused qlinear GEMMs
    dim3 grid(N_DIM / 128, M_DIM / 128);
    qgemm_kernel<0><<<grid, 256>>>(bias, s_in, zp, s_w, nullptr);       // g_xa -> g_xb
    qgemm_kernel<1><<<grid, 256>>>(bias, s_in, zp, s_w, nullptr);       // g_xb -> g_xa
    qgemm_kernel<2><<<grid, 256>>>(bias, s_in, zp, s_w, (float*)d_out); // g_xa -> out
}

// round 4
// speedup vs baseline: 1.3698x; 1.3698x over previous
#include <cuda_runtime.h>
#include <cstdint>

// Problem dims (fixed by the dataset)
#define M_DIM 8192
#define K_DIM 4096
#define N_DIM 4096

// Tiling
#define M_TILE 128
#define N_TILE 128
#define KB_TILE 128                    // K bytes (=elements) per stage
#define NT (K_DIM / KB_TILE)           // 32 mainloop iterations
#define STAGES 3
#define HALF_STAGE 16384               // 128 rows x 128 B (one matrix)
#define STAGE_BYTES (2 * HALF_STAGE)   // A + B
#define SMEM_TOTAL (STAGES * STAGE_BYTES)   // 96 KB

// ---------------------------------------------------------------------------
// Scratch: static __device__ globals (no runtime allocation allowed).
// ---------------------------------------------------------------------------
__device__ __align__(128) int8_t g_w8[(size_t)N_DIM * K_DIM];
__device__ __align__(128) int8_t g_xa[(size_t)M_DIM * K_DIM];
__device__ __align__(128) int8_t g_xb[(size_t)M_DIM * K_DIM];

// ---------------------------------------------------------------------------
// PTX helpers
// ---------------------------------------------------------------------------
__device__ __forceinline__ void cp16(uint32_t smem_dst, const void* gmem_src) {
    asm volatile("cp.async.cg.shared.global [%0], [%1], 16;\n"
                 :: "r"(smem_dst), "l"(gmem_src));
}

__device__ __forceinline__ void ldsm_x4(uint32_t& r0, uint32_t& r1, uint32_t& r2,
                                        uint32_t& r3, uint32_t addr) {
    asm volatile("ldmatrix.sync.aligned.m8n8.x4.shared.b16 {%0,%1,%2,%3}, [%4];"
                 : "=r"(r0), "=r"(r1), "=r"(r2), "=r"(r3) : "r"(addr));
}

__device__ __forceinline__ void imma16832(int* c, uint32_t a0, uint32_t a1,
                                          uint32_t a2, uint32_t a3,
                                          uint32_t b0, uint32_t b1) {
    asm volatile(
        "mma.sync.aligned.m16n8k32.row.col.s32.s8.s8.s32 "
        "{%0,%1,%2,%3}, {%4,%5,%6,%7}, {%8,%9}, {%0,%1,%2,%3};"
        : "+r"(c[0]), "+r"(c[1]), "+r"(c[2]), "+r"(c[3])
        : "r"(a0), "r"(a1), "r"(a2), "r"(a3), "r"(b0), "r"(b1));
}

// ---------------------------------------------------------------------------
// Prologue kernels
// ---------------------------------------------------------------------------
__global__ void prep_w_kernel(const int* __restrict__ w) {
    size_t i = (size_t)blockIdx.x * blockDim.x + threadIdx.x;
    size_t n4 = (size_t)N_DIM * K_DIM / 4;
    if (i < n4) {
        int4 v = reinterpret_cast<const int4*>(w)[i];
        char4 c;
        c.x = (char)v.x; c.y = (char)v.y; c.z = (char)v.z; c.w = (char)v.w;
        reinterpret_cast<char4*>(g_w8)[i] = c;
    }
}

__global__ void quant_x_kernel(const float* __restrict__ x,
                               const float* __restrict__ s_in_p,
                               const int* __restrict__ zp_p) {
    size_t i = (size_t)blockIdx.x * blockDim.x + threadIdx.x;
    size_t n4 = (size_t)M_DIM * K_DIM / 4;
    if (i >= n4) return;
    float s  = s_in_p[0];
    float zp = (float)zp_p[0];
    float lo = 0.0f - zp, hi = 255.0f - zp;
    float4 v = reinterpret_cast<const float4*>(x)[i];
    float q0 = fminf(fmaxf(rintf(__fdiv_rn(v.x, s)), lo), hi);
    float q1 = fminf(fmaxf(rintf(__fdiv_rn(v.y, s)), lo), hi);
    float q2 = fminf(fmaxf(rintf(__fdiv_rn(v.z, s)), lo), hi);
    float q3 = fminf(fmaxf(rintf(__fdiv_rn(v.w, s)), lo), hi);
    char4 c;
    c.x = (char)(int)q0; c.y = (char)(int)q1; c.z = (char)(int)q2; c.w = (char)(int)q3;
    reinterpret_cast<char4*>(g_xa)[i] = c;
}

// ---------------------------------------------------------------------------
// Int8 GEMM + fused dequant(+requant) epilogue. Legacy IMMA path (the only
// tensor path this toolchain targets: PTX is built for plain sm_100).
//
//   Block 128x128, 8 warps (2x4), warp tile 64x32.
//   3-stage cp.async ring, 128B K-chunks, XOR-swizzled 128B smem rows.
//   Fragment double-buffer: ldmatrix of k-step ks+1 overlaps IMMAs of ks.
//
//   LAYER 0: g_xa -> requant int8 g_xb
//   LAYER 1: g_xb -> requant int8 g_xa
//   LAYER 2: g_xa -> float d_out
// ---------------------------------------------------------------------------
template <int LAYER>
__global__ __launch_bounds__(256, 2)
void qgemm_kernel(const float* __restrict__ bias,
                  const float* __restrict__ s_in_p,
                  const int* __restrict__ zp_p,
                  const float* __restrict__ s_w,
                  float* __restrict__ fout) {
    extern __shared__ __align__(128) int8_t smem[];
    const uint32_t smem_b = (uint32_t)__cvta_generic_to_shared(smem);

    const int8_t* __restrict__ A = (LAYER == 1) ? g_xb : g_xa;
    int8_t* __restrict__ q_out   = (LAYER == 0) ? g_xb : g_xa;
    const int8_t* __restrict__ B = g_w8;

    const int tid  = threadIdx.x;
    const int lane = tid & 31;
    const int wid  = tid >> 5;
    const int m0 = blockIdx.y * M_TILE;
    const int n0 = blockIdx.x * N_TILE;
    const int wm = (wid >> 2) * 64;   // warp m offset within block
    const int wn = (wid & 3) * 32;    // warp n offset within block

    // ---- stage loader: A[128 x 128B] + B[128 x 128B], XOR swizzle ----
    // 16B chunk c of row r lands at r*128 + ((c ^ (r&7))<<4)  -> ldmatrix
    // over any 8 consecutive rows at fixed chunk is bank-conflict-free.
    auto load_stage = [&](int slot, int kt) {
        const uint32_t aBase = smem_b + slot * STAGE_BYTES;
        const uint32_t bBase = aBase + HALF_STAGE;
        const int kb = kt * KB_TILE;
#pragma unroll
        for (int i = 0; i < 4; i++) {
            int idx = (i << 8) + tid;          // 0..1023
            int row = idx >> 3;
            int c   = idx & 7;
            uint32_t sw = ((uint32_t)row << 7) | (uint32_t)(((c ^ (row & 7)) << 4));
            cp16(aBase + sw, A + (size_t)(m0 + row) * K_DIM + kb + c * 16);
            cp16(bBase + sw, B + (size_t)(n0 + row) * K_DIM + kb + c * 16);
        }
    };

    int acc[4][4][4];
#pragma unroll
    for (int mi = 0; mi < 4; mi++)
#pragma unroll
        for (int nj = 0; nj < 4; nj++)
#pragma unroll
            for (int r = 0; r < 4; r++) acc[mi][nj][r] = 0;

    // prefetch stages 0,1
    load_stage(0, 0);
    asm volatile("cp.async.commit_group;");
    load_stage(1, 1);
    asm volatile("cp.async.commit_group;");

    // ldmatrix per-thread address components (loop-invariant)
    const int q  = lane >> 3;       // matrix index 0..3 within x4
    const int rr = lane & 7;        // row within 8-row matrix
    const int rhalfA = q & 1, kcA = q >> 1;   // A: q -> (row-half, k-chunk)
    const int nsubB  = q >> 1, kcB = q & 1;   // B: q -> (n-sub, k-chunk)

    // fragment loader for one k32 step (ks in 0..3 within a 128B stage)
    auto load_frags = [&](uint32_t aBase, uint32_t bBase, int ks,
                          uint32_t a[4][4], uint32_t b[4][2]) {
#pragma unroll
        for (int mi = 0; mi < 4; mi++) {
            int row = wm + mi * 16 + rhalfA * 8 + rr;
            int ch  = 2 * ks + kcA;
            uint32_t addr = aBase + ((uint32_t)row << 7) + (uint32_t)(((ch ^ (row & 7)) << 4));
            ldsm_x4(a[mi][0], a[mi][1], a[mi][2], a[mi][3], addr);
        }
#pragma unroll
        for (int jp = 0; jp < 2; jp++) {
            int nrow = wn + (jp * 2 + nsubB) * 8 + rr;
            int ch   = 2 * ks + kcB;
            uint32_t addr = bBase + ((uint32_t)nrow << 7) + (uint32_t)(((ch ^ (nrow & 7)) << 4));
            ldsm_x4(b[jp * 2][0], b[jp * 2][1], b[jp * 2 + 1][0], b[jp * 2 + 1][1], addr);
        }
    };

    uint32_t afr[2][4][4];
    uint32_t bfr[2][4][2];

    int slot = 0;
    for (int kt = 0; kt < NT; kt++) {
        // stage `slot` resident
        if (kt + 2 < NT) {
            asm volatile("cp.async.wait_group 1;");
        } else {
            asm volatile("cp.async.wait_group 0;");
        }
        __syncthreads();

        // refill stage kt+2 (its slot was consumed at iteration kt-1)
        if (kt + 2 < NT) {
            int nslot = slot + 2; if (nslot >= STAGES) nslot -= STAGES;
            load_stage(nslot, kt + 2);
            asm volatile("cp.async.commit_group;");
        }

        const uint32_t aBase = smem_b + slot * STAGE_BYTES;
        const uint32_t bBase = aBase + HALF_STAGE;

        load_frags(aBase, bBase, 0, afr[0], bfr[0]);
#pragma unroll
        for (int ks = 0; ks < 4; ks++) {
            const int cur = ks & 1;
            if (ks < 3) load_frags(aBase, bBase, ks + 1, afr[cur ^ 1], bfr[cur ^ 1]);
#pragma unroll
            for (int mi = 0; mi < 4; mi++)
#pragma unroll
                for (int nj = 0; nj < 4; nj++)
                    imma16832(acc[mi][nj],
                              afr[cur][mi][0], afr[cur][mi][1],
                              afr[cur][mi][2], afr[cur][mi][3],
                              bfr[cur][nj][0], bfr[cur][nj][1]);
        }

        if (++slot >= STAGES) slot = 0;
    }

    // ---- epilogue ----
    float s  = s_in_p[0];
    float zp = (float)zp_p[0];
    float lo = 0.0f - zp, hi = 255.0f - zp;

#pragma unroll
    for (int nj = 0; nj < 4; nj++) {
        int col = n0 + wn + nj * 8 + (lane & 3) * 2;
        float sw0 = s * __ldg(&s_w[col]);
        float sw1 = s * __ldg(&s_w[col + 1]);
        float bi0 = __ldg(&bias[col]);
        float bi1 = __ldg(&bias[col + 1]);
#pragma unroll
        for (int mi = 0; mi < 4; mi++) {
            int row = m0 + wm + mi * 16 + (lane >> 2);
            float y00 = fmaf((float)acc[mi][nj][0], sw0, bi0);
            float y01 = fmaf((float)acc[mi][nj][1], sw1, bi1);
            float y10 = fmaf((float)acc[mi][nj][2], sw0, bi0);
            float y11 = fmaf((float)acc[mi][nj][3], sw1, bi1);
            if (LAYER < 2) {
                float q00 = fminf(fmaxf(rintf(__fdiv_rn(y00, s)), lo), hi);
                float q01 = fminf(fmaxf(rintf(__fdiv_rn(y01, s)), lo), hi);
                float q10 = fminf(fmaxf(rintf(__fdiv_rn(y10, s)), lo), hi);
                float q11 = fminf(fmaxf(rintf(__fdiv_rn(y11, s)), lo), hi);
                char2 c0; c0.x = (char)(int)q00; c0.y = (char)(int)q01;
                char2 c1; c1.x = (char)(int)q10; c1.y = (char)(int)q11;
                *reinterpret_cast<char2*>(q_out + (size_t)row * N_DIM + col) = c0;
                *reinterpret_cast<char2*>(q_out + (size_t)(row + 8) * N_DIM + col) = c1;
            } else {
                float2 f0; f0.x = y00; f0.y = y01;
                float2 f1; f1.x = y10; f1.y = y11;
                *reinterpret_cast<float2*>(fout + (size_t)row * N_DIM + col) = f0;
                *reinterpret_cast<float2*>(fout + (size_t)(row + 8) * N_DIM + col) = f1;
            }
        }
    }
}

// ---------------------------------------------------------------------------
// kernel_launch: graph-capturable, allocation-free, launches only.
// Input order: input, weights, biases, input_scales, input_zero_points,
//              weight_scales, weight_zero_points, output_dtype
// ---------------------------------------------------------------------------
extern "C" void kernel_launch(void* const* d_in, const int* in_sizes, int n_in,
                              void* d_out, int out_size) {
    const float* x    = (const float*)d_in[0];
    const int*   w    = (const int*)d_in[1];
    const float* bias = (const float*)d_in[2];
    const float* s_in = (const float*)d_in[3];
    const int*   zp   = (const int*)d_in[4];
    const float* s_w  = (const float*)d_in[5];

    static bool attr_done = false;
    if (!attr_done) {
        cudaFuncSetAttribute(qgemm_kernel<0>, cudaFuncAttributeMaxDynamicSharedMemorySize, SMEM_TOTAL);
        cudaFuncSetAttribute(qgemm_kernel<1>, cudaFuncAttributeMaxDynamicSharedMemorySize, SMEM_TOTAL);
        cudaFuncSetAttribute(qgemm_kernel<2>, cudaFuncAttributeMaxDynamicSharedMemorySize, SMEM_TOTAL);
        attr_done = true;
    }

    {
        size_t n4 = (size_t)N_DIM * K_DIM / 4;
        prep_w_kernel<<<(unsigned)((n4 + 255) / 256), 256>>>(w);
    }
    {
        size_t n4 = (size_t)M_DIM * K_DIM / 4;
        quant_x_kernel<<<(unsigned)((n4 + 255) / 256), 256>>>(x, s_in, zp);
    }

    dim3 grid(N_DIM / N_TILE, M_DIM / M_TILE);   // 32 x 64 = 2048 CTAs
    qgemm_kernel<0><<<grid, 256, SMEM_TOTAL>>>(bias, s_in, zp, s_w, nullptr);
    qgemm_kernel<1><<<grid, 256, SMEM_TOTAL>>>(bias, s_in, zp, s_w, nullptr);
    qgemm_kernel<2><<<grid, 256, SMEM_TOTAL>>>(bias, s_in, zp, s_w, (float*)d_out);
}